// round 16
// baseline (speedup 1.0000x reference)
#include <cuda_runtime.h>
#include <math_constants.h>

// N = 4096 mention-ranking loss, one streaming pass, row-paired CTAs.
// R13 proven-best skeleton (12.768us: 2048x128, occ 14, float4 mask +
// 16B-lane-stride scalar ana, 4-group unroll, predicated accumulate).
// Delta: streaming loads use ld.global.cg (L2-only, bypass L1) -- both
// streams are single-touch per launch, so L1 allocation is pure overhead.

#define NMENT 4096
#define BLOCK 128

__device__ __forceinline__ float4 ldcg4(const float4* p)
{
    float4 v;
    asm("ld.global.cg.v4.f32 {%0,%1,%2,%3}, [%4];"
        : "=f"(v.x), "=f"(v.y), "=f"(v.z), "=f"(v.w) : "l"(p));
    return v;
}
__device__ __forceinline__ float ldcg1(const float* p)
{
    float v;
    asm("ld.global.cg.f32 %0, [%1];" : "=f"(v) : "l"(p));
    return v;
}

__device__ __forceinline__ void acc_one(float m, float s, float& bestM, float& maxU)
{
    if (m > 0.5f) bestM = fmaxf(bestM, s);
    else          maxU  = fmaxf(maxU,  s);
}

__device__ __forceinline__ void acc_g4(const float4 m, const float* __restrict__ a,
                                       int j, float& bestM, float& maxU)
{
    const float s0 = ldcg1(a + j + 0);
    const float s1 = ldcg1(a + j + 1);
    const float s2 = ldcg1(a + j + 2);
    const float s3 = ldcg1(a + j + 3);
    acc_one(m.x, s0, bestM, maxU);
    acc_one(m.y, s1, bestM, maxU);
    acc_one(m.z, s2, bestM, maxU);
    acc_one(m.w, s3, bestM, maxU);
}

__global__ __launch_bounds__(BLOCK, 14)
void mention_loss_kernel(const float* __restrict__ eps_scores,
                         const float* __restrict__ ana_scores,
                         const float* __restrict__ mask,
                         const float* __restrict__ link_costs,
                         const float* __restrict__ false_new_cost,
                         float* __restrict__ out)
{
    const int b    = (int)blockIdx.x;        // 0..2047
    const int tid  = (int)threadIdx.x;
    const int warp = tid >> 5;
    const int lane = tid & 31;

    __shared__ float sM[2][BLOCK / 32];
    __shared__ float sU[2][BLOCK / 32];

    const float lc0 = __ldg(link_costs + 0);    // false_link
    const float lc1 = __ldg(link_costs + 1);    // wrong_link
    const float fnc = __ldg(false_new_cost);

    #pragma unroll
    for (int r = 0; r < 2; ++r) {
        const int row = (r == 0) ? b : (NMENT - 1 - b);

        const float* __restrict__ mrow = mask + (size_t)row * NMENT;   // 16B-aligned
        const long long abase = ((long long)row * (row - 1)) >> 1;
        const float* __restrict__ arow = ana_scores + abase;

        float bestM = -CUDART_INF_F;
        float maxU  = -CUDART_INF_F;

        const int nv = row >> 2;               // full float4 groups
        const float4* __restrict__ mrow4 = (const float4*)mrow;

        int v = tid;
        for (; v + 3 * BLOCK < nv; v += 4 * BLOCK) {
            const float4 q0 = ldcg4(mrow4 + v);
            const float4 q1 = ldcg4(mrow4 + v + BLOCK);
            const float4 q2 = ldcg4(mrow4 + v + 2 * BLOCK);
            const float4 q3 = ldcg4(mrow4 + v + 3 * BLOCK);
            acc_g4(q0, arow, v << 2,                 bestM, maxU);
            acc_g4(q1, arow, (v + BLOCK) << 2,       bestM, maxU);
            acc_g4(q2, arow, (v + 2 * BLOCK) << 2,   bestM, maxU);
            acc_g4(q3, arow, (v + 3 * BLOCK) << 2,   bestM, maxU);
        }
        for (; v < nv; v += BLOCK) {
            const float4 q0 = ldcg4(mrow4 + v);
            acc_g4(q0, arow, v << 2, bestM, maxU);
        }
        // Scalar tail: j in [nv*4, row)
        for (int j = (nv << 2) + tid; j < row; j += BLOCK) {
            acc_one(ldcg1(mrow + j), ldcg1(arow + j), bestM, maxU);
        }

        // Warp reduction
        #pragma unroll
        for (int off = 16; off > 0; off >>= 1) {
            bestM = fmaxf(bestM, __shfl_xor_sync(0xffffffffu, bestM, off));
            maxU  = fmaxf(maxU,  __shfl_xor_sync(0xffffffffu, maxU,  off));
        }
        if (lane == 0) { sM[r][warp] = bestM; sU[r][warp] = maxU; }
    }

    __syncthreads();

    // One warp finalizes both rows (4 partials each).
    if (warp == 0 && lane < 2) {
        const int r   = lane;
        const int row = (r == 0) ? b : (NMENT - 1 - b);

        float bestM = fmaxf(fmaxf(sM[r][0], sM[r][1]), fmaxf(sM[r][2], sM[r][3]));
        float maxU  = fmaxf(fmaxf(sU[r][0], sU[r][1]), fmaxf(sU[r][2], sU[r][3]));

        const float nonana = __ldg(mask + (size_t)row * NMENT + row);   // diag
        const float e      = __ldg(eps_scores + row);
        if (nonana > 0.5f) bestM = fmaxf(bestM, e);

        const float row_cost = nonana * lc0 + (1.0f - nonana) * lc1;

        float loss = 0.0f;
        loss = fmaxf(loss, row_cost * (1.0f + maxU - bestM));   // -inf-safe
        const float dcost = (1.0f - nonana) * fnc;
        loss = fmaxf(loss, dcost * (1.0f + e - bestM));

        out[row] = loss;
    }
}

extern "C" void kernel_launch(void* const* d_in, const int* in_sizes, int n_in,
                              void* d_out, int out_size)
{
    const float* eps  = (const float*)d_in[0];
    const float* ana  = (const float*)d_in[1];
    const float* mask = (const float*)d_in[2];
    const float* lc   = (const float*)d_in[3];
    const float* fnc  = (const float*)d_in[4];
    float* out = (float*)d_out;

    mention_loss_kernel<<<NMENT / 2, BLOCK>>>(eps, ana, mask, lc, fnc, out);
}

// round 17
// speedup vs baseline: 1.2130x; 1.2130x over previous
#include <cuda_runtime.h>
#include <math_constants.h>

// N = 4096 mention-ranking loss — FINAL (proven optimum, 12.768us x2).
//
// Math collapse: the reference's NxN score matrix + min/max dance reduces to,
// per row i: bestM = max over masked entries (tril from ana_scores, diag from
// eps), maxU = max over unmasked strict-lower entries; then
//   loss_i = max(0, row_cost*(1+maxU-bestM), (1-mask_ii)*fnc*(1+eps_i-bestM)).
// One streaming pass over tril(mask) + ana_scores (~67MB), nothing else.
//
// Winning configuration (16-round sweep):
//  - CTA b handles rows {b, 4095-b}: uniform ~4095 elems/CTA, no ragged tail.
//  - 2048 CTAs x 128 threads, occupancy 14 -> near single-wave, 48 warps/SM.
//  - mask rows 16B-aligned -> float4 LDG.128; ana rows unaligned -> 4 scalar
//    LDG.32 at 16B lane stride (L1 sector hits make this the fastest form;
//    .cg bypass, v8, shfl-sharing, cp.async all measured slower).
//  - 4-group unrolled main loop (20 loads in flight/thread).
//  - predicated FMNMX accumulate (measured faster than branchless FFMA).

#define NMENT 4096
#define BLOCK 128

__device__ __forceinline__ void acc_one(float m, float s, float& bestM, float& maxU)
{
    if (m > 0.5f) bestM = fmaxf(bestM, s);
    else          maxU  = fmaxf(maxU,  s);
}

__device__ __forceinline__ void acc_g4(const float4 m, const float* __restrict__ a,
                                       int j, float& bestM, float& maxU)
{
    const float s0 = __ldg(a + j + 0);
    const float s1 = __ldg(a + j + 1);
    const float s2 = __ldg(a + j + 2);
    const float s3 = __ldg(a + j + 3);
    acc_one(m.x, s0, bestM, maxU);
    acc_one(m.y, s1, bestM, maxU);
    acc_one(m.z, s2, bestM, maxU);
    acc_one(m.w, s3, bestM, maxU);
}

__global__ __launch_bounds__(BLOCK, 14)
void mention_loss_kernel(const float* __restrict__ eps_scores,
                         const float* __restrict__ ana_scores,
                         const float* __restrict__ mask,
                         const float* __restrict__ link_costs,
                         const float* __restrict__ false_new_cost,
                         float* __restrict__ out)
{
    const int b    = (int)blockIdx.x;        // 0..2047
    const int tid  = (int)threadIdx.x;
    const int warp = tid >> 5;
    const int lane = tid & 31;

    __shared__ float sM[2][BLOCK / 32];
    __shared__ float sU[2][BLOCK / 32];

    const float lc0 = __ldg(link_costs + 0);    // false_link
    const float lc1 = __ldg(link_costs + 1);    // wrong_link
    const float fnc = __ldg(false_new_cost);

    #pragma unroll
    for (int r = 0; r < 2; ++r) {
        const int row = (r == 0) ? b : (NMENT - 1 - b);

        const float* __restrict__ mrow = mask + (size_t)row * NMENT;   // 16B-aligned
        const long long abase = ((long long)row * (row - 1)) >> 1;
        const float* __restrict__ arow = ana_scores + abase;

        float bestM = -CUDART_INF_F;
        float maxU  = -CUDART_INF_F;

        const int nv = row >> 2;               // full float4 groups
        const float4* __restrict__ mrow4 = (const float4*)mrow;

        int v = tid;
        // 4-group deep main loop: 4 x LDG.128 + 16 x LDG.32 in flight.
        for (; v + 3 * BLOCK < nv; v += 4 * BLOCK) {
            const float4 q0 = __ldg(mrow4 + v);
            const float4 q1 = __ldg(mrow4 + v + BLOCK);
            const float4 q2 = __ldg(mrow4 + v + 2 * BLOCK);
            const float4 q3 = __ldg(mrow4 + v + 3 * BLOCK);
            acc_g4(q0, arow, v << 2,                 bestM, maxU);
            acc_g4(q1, arow, (v + BLOCK) << 2,       bestM, maxU);
            acc_g4(q2, arow, (v + 2 * BLOCK) << 2,   bestM, maxU);
            acc_g4(q3, arow, (v + 3 * BLOCK) << 2,   bestM, maxU);
        }
        for (; v < nv; v += BLOCK) {
            const float4 q0 = __ldg(mrow4 + v);
            acc_g4(q0, arow, v << 2, bestM, maxU);
        }
        // Scalar tail: j in [nv*4, row)
        for (int j = (nv << 2) + tid; j < row; j += BLOCK) {
            acc_one(__ldg(mrow + j), __ldg(arow + j), bestM, maxU);
        }

        // Warp reduction
        #pragma unroll
        for (int off = 16; off > 0; off >>= 1) {
            bestM = fmaxf(bestM, __shfl_xor_sync(0xffffffffu, bestM, off));
            maxU  = fmaxf(maxU,  __shfl_xor_sync(0xffffffffu, maxU,  off));
        }
        if (lane == 0) { sM[r][warp] = bestM; sU[r][warp] = maxU; }
    }

    __syncthreads();

    // One warp finalizes both rows (4 partials each).
    if (warp == 0 && lane < 2) {
        const int r   = lane;
        const int row = (r == 0) ? b : (NMENT - 1 - b);

        float bestM = fmaxf(fmaxf(sM[r][0], sM[r][1]), fmaxf(sM[r][2], sM[r][3]));
        float maxU  = fmaxf(fmaxf(sU[r][0], sU[r][1]), fmaxf(sU[r][2], sU[r][3]));

        const float nonana = __ldg(mask + (size_t)row * NMENT + row);   // diag
        const float e      = __ldg(eps_scores + row);
        if (nonana > 0.5f) bestM = fmaxf(bestM, e);

        const float row_cost = nonana * lc0 + (1.0f - nonana) * lc1;

        float loss = 0.0f;
        loss = fmaxf(loss, row_cost * (1.0f + maxU - bestM));   // -inf-safe
        const float dcost = (1.0f - nonana) * fnc;
        loss = fmaxf(loss, dcost * (1.0f + e - bestM));

        out[row] = loss;
    }
}

extern "C" void kernel_launch(void* const* d_in, const int* in_sizes, int n_in,
                              void* d_out, int out_size)
{
    const float* eps  = (const float*)d_in[0];
    const float* ana  = (const float*)d_in[1];
    const float* mask = (const float*)d_in[2];
    const float* lc   = (const float*)d_in[3];
    const float* fnc  = (const float*)d_in[4];
    float* out = (float*)d_out;

    mention_loss_kernel<<<NMENT / 2, BLOCK>>>(eps, ana, mask, lc, fnc, out);
}